// round 7
// baseline (speedup 1.0000x reference)
#include <cuda_runtime.h>
#include <cuda_fp16.h>

#define B_TOTAL 65536
#define DD      256
#define HH      16
#define TPB     224

// tanh.approx.f16x2: one MUFU op evaluates tanh on both fp16 lanes.
__device__ __forceinline__ __half2 tanh_h2(__half2 v) {
    unsigned u = *reinterpret_cast<unsigned*>(&v);
    unsigned y;
    asm("tanh.approx.f16x2 %0, %1;" : "=r"(y) : "r"(u));
    return *reinterpret_cast<__half2*>(&y);
}

__device__ __forceinline__ __half2 ld_h2(const unsigned& u) {
    return *reinterpret_cast<const __half2*>(&u);
}

__global__ void __launch_bounds__(TPB, 2) kan_kernel(
    const float* __restrict__ x,
    const float* __restrict__ w1,
    const float* __restrict__ b1,
    const float* __restrict__ w2,
    const float* __restrict__ b2,
    float* __restrict__ out)
{
    // Params as half2: 3 * 256 * 8 * 4B = 24 KB shared (2 blocks/SM -> 48 KB)
    __shared__ unsigned sw1[DD * HH / 2];
    __shared__ unsigned sb1[DD * HH / 2];
    __shared__ unsigned sw2[DD * HH / 2];

    {
        const float2* gw1 = reinterpret_cast<const float2*>(w1);
        const float2* gb1 = reinterpret_cast<const float2*>(b1);
        const float2* gw2 = reinterpret_cast<const float2*>(w2);
        for (int i = threadIdx.x; i < DD * HH / 2; i += TPB) {
            __half2 a = __float22half2_rn(gw1[i]);
            __half2 b = __float22half2_rn(gb1[i]);
            __half2 c = __float22half2_rn(gw2[i]);
            sw1[i] = *reinterpret_cast<unsigned*>(&a);
            sb1[i] = *reinterpret_cast<unsigned*>(&b);
            sw2[i] = *reinterpret_cast<unsigned*>(&c);
        }
    }
    __syncthreads();

    const int b = blockIdx.x * TPB + threadIdx.x;
    if (b >= B_TOTAL) return;

    // sum(b2): uniform-address loads, L1-resident, negligible.
    float accb = 0.0f;
    const float4* gb2 = reinterpret_cast<const float4*>(b2);
    #pragma unroll
    for (int i = 0; i < DD / 4; ++i) {
        float4 v = __ldg(&gb2[i]);
        accb += (v.x + v.y) + (v.z + v.w);
    }

    const float4* xr = reinterpret_cast<const float4*>(x + (size_t)b * DD);

    float acc0 = 0.0f, acc1 = 0.0f;

    float4 nxt = xr[0];   // software prefetch, distance 1
    #pragma unroll 1
    for (int d4 = 0; d4 < DD / 4; ++d4) {
        float4 xv = nxt;
        if (d4 + 1 < DD / 4) nxt = xr[d4 + 1];

        float xs[4] = {xv.x, xv.y, xv.z, xv.w};
        #pragma unroll
        for (int j = 0; j < 4; ++j) {
            const int d = d4 * 4 + j;
            const __half2 xh = __float2half2_rn(xs[j]);

            // 16 h's of this d: 8 half2 per array, 2 x LDS.128 each
            const uint4 A0 = *reinterpret_cast<const uint4*>(&sw1[d * 8]);
            const uint4 A1 = *reinterpret_cast<const uint4*>(&sw1[d * 8 + 4]);
            const uint4 B0 = *reinterpret_cast<const uint4*>(&sb1[d * 8]);
            const uint4 B1 = *reinterpret_cast<const uint4*>(&sb1[d * 8 + 4]);
            const uint4 C0 = *reinterpret_cast<const uint4*>(&sw2[d * 8]);
            const uint4 C1 = *reinterpret_cast<const uint4*>(&sw2[d * 8 + 4]);

            // h = tanh(x*w1 + b1)   (8 HFMA2 + 8 MUFU.f16x2)
            __half2 t0 = tanh_h2(__hfma2(xh, ld_h2(A0.x), ld_h2(B0.x)));
            __half2 t1 = tanh_h2(__hfma2(xh, ld_h2(A0.y), ld_h2(B0.y)));
            __half2 t2 = tanh_h2(__hfma2(xh, ld_h2(A0.z), ld_h2(B0.z)));
            __half2 t3 = tanh_h2(__hfma2(xh, ld_h2(A0.w), ld_h2(B0.w)));
            __half2 t4 = tanh_h2(__hfma2(xh, ld_h2(A1.x), ld_h2(B1.x)));
            __half2 t5 = tanh_h2(__hfma2(xh, ld_h2(A1.y), ld_h2(B1.y)));
            __half2 t6 = tanh_h2(__hfma2(xh, ld_h2(A1.z), ld_h2(B1.z)));
            __half2 t7 = tanh_h2(__hfma2(xh, ld_h2(A1.w), ld_h2(B1.w)));

            // p = h * w2            (8 HMUL2)
            __half2 p0 = __hmul2(t0, ld_h2(C0.x));
            __half2 p1 = __hmul2(t1, ld_h2(C0.y));
            __half2 p2 = __hmul2(t2, ld_h2(C0.z));
            __half2 p3 = __hmul2(t3, ld_h2(C0.w));
            __half2 p4 = __hmul2(t4, ld_h2(C1.x));
            __half2 p5 = __hmul2(t5, ld_h2(C1.y));
            __half2 p6 = __hmul2(t6, ld_h2(C1.z));
            __half2 p7 = __hmul2(t7, ld_h2(C1.w));

            // lanewise tree reduce over the 8 half2 (7 HADD2);
            // partial magnitudes <= 8*0.25 = 2, safe in fp16
            __half2 s0 = __hadd2(p0, p1);
            __half2 s1 = __hadd2(p2, p3);
            __half2 s2 = __hadd2(p4, p5);
            __half2 s3 = __hadd2(p6, p7);
            s0 = __hadd2(s0, s1);
            s2 = __hadd2(s2, s3);
            s0 = __hadd2(s0, s2);   // (sum of even h, sum of odd h)

            // only 2 F2F per 16 elements
            float2 f = __half22float2(s0);
            acc0 += f.x;
            acc1 += f.y;
        }
    }

    out[b] = (acc0 + acc1) + accb;
}

extern "C" void kernel_launch(void* const* d_in, const int* in_sizes, int n_in,
                              void* d_out, int out_size) {
    const float* x  = (const float*)d_in[0];
    const float* w1 = (const float*)d_in[1];
    const float* b1 = (const float*)d_in[2];
    const float* w2 = (const float*)d_in[3];
    const float* b2 = (const float*)d_in[4];
    float* out = (float*)d_out;

    const int nblk = (B_TOTAL + TPB - 1) / TPB;   // 293 blocks -> 2 blocks/SM
    kan_kernel<<<nblk, TPB>>>(x, w1, b1, w2, b2, out);
}

// round 9
// speedup vs baseline: 1.1663x; 1.1663x over previous
#include <cuda_runtime.h>

#define B_TOTAL 65536
#define DD      256
#define HH      16
#define NKNOT   53          // knots at XMIN + k*HSTEP, k=0..52  (covers [-6.5, 6.5])
#define TPB     448
#define XMIN    (-6.5f)
#define HSTEP   0.25f
#define INV_H   4.0f
#define TBL_ELEMS (DD * NKNOT)          // 13568 float4
#define TBL_BYTES (TBL_ELEMS * 16)      // 217088 B dynamic smem

// Per-d per-knot Taylor cubic coefficients (c0,c1,c2,c3), frac in knot units in [-0.5, 0.5]
__device__ float4 g_table[TBL_ELEMS];

__device__ __forceinline__ float tanhA(float v) {
    float y;
    asm("tanh.approx.f32 %0, %1;" : "=f"(y) : "f"(v));
    return y;
}

// Build: phi_d(x) = sum_h tanh(x*w1+b1)*w2 + b2[d]; analytic derivatives from tanh.
__global__ void build_table(const float* __restrict__ w1, const float* __restrict__ b1,
                            const float* __restrict__ w2, const float* __restrict__ b2)
{
    const int d = blockIdx.x;
    const int k = threadIdx.x;
    if (k >= NKNOT) return;

    const float xk = XMIN + HSTEP * (float)k;
    float v = 0.0f, s1 = 0.0f, s2 = 0.0f, s3 = 0.0f;
    #pragma unroll
    for (int h = 0; h < HH; ++h) {
        const float W1 = w1[d * HH + h];
        const float B1 = b1[d * HH + h];
        const float W2 = w2[d * HH + h];
        const float T  = tanhA(fmaf(xk, W1, B1));
        const float T2 = T * T;
        const float u  = 1.0f - T2;              // sech^2
        const float w2w1 = W2 * W1;
        v  = fmaf(W2, T, v);                      // phi
        s1 = fmaf(w2w1, u, s1);                   // phi'
        s2 = fmaf(w2w1 * W1, -2.0f * T * u, s2);  // phi''
        s3 = fmaf(w2w1 * W1 * W1, (6.0f * T2 - 2.0f) * u, s3);  // phi'''
    }
    float4 c;
    c.x = v + b2[d];                              // fold b2 into c0 (summed over d later)
    c.y = s1 * HSTEP;                             // frac-units scaling
    c.z = s2 * (0.5f * HSTEP * HSTEP);
    c.w = s3 * (HSTEP * HSTEP * HSTEP * (1.0f / 6.0f));
    g_table[d * NKNOT + k] = c;
}

__global__ void __launch_bounds__(TPB, 1) kan_main(
    const float* __restrict__ x, float* __restrict__ out)
{
    extern __shared__ float4 smtab[];   // [DD * NKNOT]

    for (int i = threadIdx.x; i < TBL_ELEMS; i += TPB)
        smtab[i] = g_table[i];
    __syncthreads();

    const int b = blockIdx.x * TPB + threadIdx.x;
    if (b >= B_TOTAL) return;

    const float4* xr = reinterpret_cast<const float4*>(x + (size_t)b * DD);

    const float MAGIC = 8388608.0f;     // 2^23: round-to-nearest integer extraction
    float acc0 = 0.0f, acc1 = 0.0f, acc2 = 0.0f, acc3 = 0.0f;

    float4 nxt = xr[0];                 // software prefetch, distance 1
    #pragma unroll 1
    for (int d4 = 0; d4 < DD / 4; ++d4) {
        float4 xv = nxt;
        if (d4 + 1 < DD / 4) nxt = xr[d4 + 1];

        float xs[4] = {xv.x, xv.y, xv.z, xv.w};
        float ys[4];
        #pragma unroll
        for (int j = 0; j < 4; ++j) {
            const int d = d4 * 4 + j;
            // t = (x - XMIN)/h  in [0, 52], clamped
            float t = fmaf(xs[j], INV_H, -XMIN * INV_H);
            t = fminf(fmaxf(t, 0.0f), 52.0f);
            // nearest knot via 2^23 trick: no F2I/I2F in the hot loop
            const float fm = __fadd_rn(t, MAGIC);
            const int  idx = __float_as_int(fm) & 0xFFFF;     // rne(t) in [0,52]
            const float fi = __fadd_rn(fm, -MAGIC);
            const float fr = t - fi;                          // [-0.5, 0.5] knot units

            const float4 c = smtab[d * NKNOT + idx];
            float y = fmaf(c.w, fr, c.z);
            y = fmaf(y, fr, c.y);
            ys[j] = fmaf(y, fr, c.x);
        }
        acc0 += ys[0];
        acc1 += ys[1];
        acc2 += ys[2];
        acc3 += ys[3];
    }

    out[b] = (acc0 + acc1) + (acc2 + acc3);
}

extern "C" void kernel_launch(void* const* d_in, const int* in_sizes, int n_in,
                              void* d_out, int out_size) {
    const float* x  = (const float*)d_in[0];
    const float* w1 = (const float*)d_in[1];
    const float* b1 = (const float*)d_in[2];
    const float* w2 = (const float*)d_in[3];
    const float* b2 = (const float*)d_in[4];
    float* out = (float*)d_out;

    build_table<<<DD, 64>>>(w1, b1, w2, b2);

    cudaFuncSetAttribute(kan_main, cudaFuncAttributeMaxDynamicSharedMemorySize, TBL_BYTES);
    const int nblk = (B_TOTAL + TPB - 1) / TPB;   // 147 blocks -> one wave on 148 SMs
    kan_main<<<nblk, TPB, TBL_BYTES>>>(x, out);
}